// round 1
// baseline (speedup 1.0000x reference)
#include <cuda_runtime.h>

#define D_COLS   4096
#define K_SEL    2048
#define NTHREADS 256
#define VPT      16               // values per thread = D_COLS / NTHREADS
#define NWARP    (NTHREADS / 32)
#define CAND_MAX 128

// Monotone float <-> ordered-uint key mapping (total order matching float <)
__device__ __forceinline__ unsigned fkey(float f) {
    unsigned u = __float_as_uint(f);
    return u ^ ((u & 0x80000000u) ? 0xFFFFFFFFu : 0x80000000u);
}
__device__ __forceinline__ float funkey(unsigned k) {
    unsigned u = k ^ ((k & 0x80000000u) ? 0x80000000u : 0xFFFFFFFFu);
    return __uint_as_float(u);
}

__global__ __launch_bounds__(NTHREADS) void sparsify1d_kernel(
    const float* __restrict__ x, float* __restrict__ out)
{
    __shared__ int   s_redi[NWARP];
    __shared__ float s_redf[NWARP];
    __shared__ float s_minr[NWARP];
    __shared__ float s_maxr[NWARP];
    __shared__ float s_thresh;
    __shared__ int   s_ncand;
    __shared__ float s_cand[CAND_MAX];

    const int t    = threadIdx.x;
    const int lane = t & 31;
    const int wid  = t >> 5;
    const long long row = blockIdx.x;

    const float4* __restrict__ xr   = (const float4*)(x + row * (long long)D_COLS);
    float4* __restrict__       orow = (float4*)(out + row * (long long)D_COLS);

    // ---- load row into registers (coalesced float4) ----
    float v[VPT];
    #pragma unroll
    for (int i = 0; i < 4; i++) {
        float4 f4 = xr[t + i * NTHREADS];
        v[4*i+0] = f4.x; v[4*i+1] = f4.y; v[4*i+2] = f4.z; v[4*i+3] = f4.w;
    }

    // ---- row min/max (for interpolation bracket) ----
    float vmin = v[0], vmax = v[0];
    #pragma unroll
    for (int i = 1; i < VPT; i++) { vmin = fminf(vmin, v[i]); vmax = fmaxf(vmax, v[i]); }
    #pragma unroll
    for (int o = 16; o > 0; o >>= 1) {
        vmin = fminf(vmin, __shfl_xor_sync(0xffffffffu, vmin, o));
        vmax = fmaxf(vmax, __shfl_xor_sync(0xffffffffu, vmax, o));
    }
    if (lane == 0) { s_minr[wid] = vmin; s_maxr[wid] = vmax; }
    __syncthreads();
    float rmin = s_minr[0], rmax = s_maxr[0];
    #pragma unroll
    for (int i = 1; i < NWARP; i++) {
        rmin = fminf(rmin, s_minr[i]);
        rmax = fmaxf(rmax, s_maxr[i]);
    }

    // ---- bracket: count(>=lo)=clo >= K > chi=count(>=hi) ----
    float lo = rmin;                     int clo = D_COLS;
    float hi = funkey(fkey(rmax) + 1u);  int chi = 0;   // just above max -> count 0

    float thresh = 0.f;
    bool  have_thresh = false;

    for (int iter = 0; iter < 64; iter++) {
        int m = clo - chi;
        if (m <= CAND_MAX) break;                 // small candidate set: finish by gather

        unsigned klo = fkey(lo), khi = fkey(hi);
        if (khi - klo <= 1u) {                    // no interior point: all candidates == lo
            thresh = lo; have_thresh = true; break;
        }

        float T = lo;
        bool ok = false;
        if (iter < 8) {                           // interpolation phase
            float frac = (float)(clo - K_SEL) / (float)m;
            T = lo + (hi - lo) * frac;
            ok = (T > lo) && (T < hi);            // also rejects NaN/degenerate
        }
        if (!ok) {                                // guaranteed-progress bisection (key space)
            T = funkey(klo + ((khi - klo) >> 1u));
        }

        // block count of (v >= T); all threads compute identical T -> uniform control
        int c = 0;
        #pragma unroll
        for (int i = 0; i < VPT; i++) c += (v[i] >= T);
        #pragma unroll
        for (int o = 16; o > 0; o >>= 1) c += __shfl_xor_sync(0xffffffffu, c, o);
        __syncthreads();                          // protect s_redi reuse
        if (lane == 0) s_redi[wid] = c;
        __syncthreads();
        c = 0;
        #pragma unroll
        for (int i = 0; i < NWARP; i++) c += s_redi[i];

        if (c >= K_SEL) { lo = T; clo = c; }
        else            { hi = T; chi = c; }
    }

    if (!have_thresh) {
        // ---- gather candidates in [lo, hi) and pick exact (K - chi)-th largest ----
        if (t == 0) s_ncand = 0;
        __syncthreads();
        #pragma unroll
        for (int i = 0; i < VPT; i++) {
            float f = v[i];
            if (f >= lo && f < hi) {
                int idx = atomicAdd(&s_ncand, 1);
                if (idx < CAND_MAX) s_cand[idx] = f;
            }
        }
        __syncthreads();
        int m = s_ncand;              // == clo - chi  (<= CAND_MAX)
        int j = K_SEL - chi;          // 1-indexed rank (descending) among candidates
        if (t < m) {
            float vi = s_cand[t];
            int gt = 0, ge = 0;
            for (int c2 = 0; c2 < m; c2++) {
                float fc = s_cand[c2];
                gt += (fc >  vi);
                ge += (fc >= vi);
            }
            if (gt < j && j <= ge) s_thresh = vi;   // unique value; ties write same bits
        }
        __syncthreads();
        thresh = s_thresh;
    }

    // ---- masked sum -> scale ----
    float s = 0.f;
    #pragma unroll
    for (int i = 0; i < VPT; i++) s += (v[i] >= thresh) ? v[i] : 0.f;
    #pragma unroll
    for (int o = 16; o > 0; o >>= 1) s += __shfl_xor_sync(0xffffffffu, s, o);
    __syncthreads();                  // protect s_redf (also orders prior s_cand reads)
    if (lane == 0) s_redf[wid] = s;
    __syncthreads();
    float tot = 0.f;
    #pragma unroll
    for (int i = 0; i < NWARP; i++) tot += s_redf[i];

    float scale = (float)D_COLS / tot;   // out = res / (sum/D) = res * D / sum

    // ---- masked scale + coalesced store ----
    #pragma unroll
    for (int i = 0; i < 4; i++) {
        float4 o;
        o.x = (v[4*i+0] >= thresh) ? v[4*i+0] * scale : 0.f;
        o.y = (v[4*i+1] >= thresh) ? v[4*i+1] * scale : 0.f;
        o.z = (v[4*i+2] >= thresh) ? v[4*i+2] * scale : 0.f;
        o.w = (v[4*i+3] >= thresh) ? v[4*i+3] * scale : 0.f;
        orow[t + i * NTHREADS] = o;
    }
}

extern "C" void kernel_launch(void* const* d_in, const int* in_sizes, int n_in,
                              void* d_out, int out_size)
{
    const float* x = (const float*)d_in[0];
    float* out     = (float*)d_out;
    int rows = in_sizes[0] / D_COLS;     // 16384
    sparsify1d_kernel<<<rows, NTHREADS>>>(x, out);
}

// round 3
// speedup vs baseline: 1.2400x; 1.2400x over previous
#include <cuda_runtime.h>

#define D_COLS   4096
#define K_SEL    2048
#define NTHREADS 256
#define VPT      16               // D_COLS / NTHREADS
#define NWARP    (NTHREADS / 32)
#define CAND_MAX 128

// Monotone float <-> ordered-uint key mapping (total order matching float <)
__device__ __forceinline__ unsigned fkey(float f) {
    unsigned u = __float_as_uint(f);
    return u ^ ((u & 0x80000000u) ? 0xFFFFFFFFu : 0x80000000u);
}
__device__ __forceinline__ float funkey(unsigned k) {
    unsigned u = k ^ ((k & 0x80000000u) ? 0x80000000u : 0xFFFFFFFFu);
    return __uint_as_float(u);
}
__device__ __forceinline__ bool my_finite(float f) { return fabsf(f) < 3.0e38f; }

__global__ __launch_bounds__(NTHREADS) void sparsify1d_kernel(
    const float* __restrict__ x, float* __restrict__ out)
{
    __shared__ int   s_redi[2][NWARP];
    __shared__ float s_redf[NWARP];
    __shared__ float s_thresh;
    __shared__ int   s_ncand;
    __shared__ float s_cand[CAND_MAX];

    const int t    = threadIdx.x;
    const int lane = t & 31;
    const int wid  = t >> 5;
    const long long row = blockIdx.x;

    const float4* __restrict__ xr   = (const float4*)(x + row * (long long)D_COLS);
    float4* __restrict__       orow = (float4*)(out + row * (long long)D_COLS);

    // ---- load row into registers + fused count at T0 = 0 ----
    float v[VPT];
    #pragma unroll
    for (int i = 0; i < 4; i++) {
        float4 f4 = xr[t + i * NTHREADS];
        v[4*i+0] = f4.x; v[4*i+1] = f4.y; v[4*i+2] = f4.z; v[4*i+3] = f4.w;
    }
    int c0 = 0;
    #pragma unroll
    for (int i = 0; i < VPT; i++) c0 += (v[i] >= 0.0f);
    c0 = __reduce_add_sync(0xffffffffu, c0);          // REDUX.SUM
    if (lane == 0) s_redi[0][wid] = c0;
    __syncthreads();
    c0 = 0;
    #pragma unroll
    for (int i = 0; i < NWARP; i++) c0 += s_redi[0][i];

    // ---- bracket: count(>=lo)=clo >= K > chi=count(>=hi) ----
    float lo, hi; int clo, chi;
    if (c0 >= K_SEL) { lo = 0.0f; clo = c0;     hi = __int_as_float(0x7f800000); chi = 0; }
    else             { hi = 0.0f; chi = c0;     lo = __int_as_float(0xff800000); clo = D_COLS; }

    float thresh = 0.f;
    bool  have_thresh = false;
    int   par = 1;

    for (int iter = 0; iter < 48; iter++) {
        int m = clo - chi;
        if (m <= CAND_MAX) break;

        unsigned klo = fkey(lo), khi = fkey(hi);
        if (khi - klo <= 1u) { thresh = lo; have_thresh = true; break; }

        float T = lo;
        bool ok = false;
        if (iter < 10) {
            bool lof = my_finite(lo), hif = my_finite(hi);
            if (lof && hif) {
                // linear interpolation on counts inside the bracket
                T = lo + (hi - lo) * ((float)(clo - K_SEL) / (float)m);
            } else if (lof) {
                // Newton step using Gaussian density at lo
                float dens = (float)D_COLS * 0.39894228f * __expf(-0.5f * lo * lo);
                T = lo + (float)(clo - K_SEL) / dens;
            } else {
                float dens = (float)D_COLS * 0.39894228f * __expf(-0.5f * hi * hi);
                T = hi - (float)(K_SEL - chi) / dens;
            }
            ok = (T > lo) && (T < hi);            // rejects NaN / no-progress
        }
        if (!ok) T = funkey(klo + ((khi - klo) >> 1u));   // guaranteed progress

        int cc = 0;
        #pragma unroll
        for (int i = 0; i < VPT; i++) cc += (v[i] >= T);
        cc = __reduce_add_sync(0xffffffffu, cc);
        if (lane == 0) s_redi[par][wid] = cc;
        __syncthreads();
        cc = 0;
        #pragma unroll
        for (int i = 0; i < NWARP; i++) cc += s_redi[par][i];
        par ^= 1;

        if (cc >= K_SEL) { lo = T; clo = cc; }
        else             { hi = T; chi = cc; }
    }

    if (!have_thresh) {
        // ---- gather candidates in [lo, hi) and pick exact (K - chi)-th largest ----
        if (t == 0) s_ncand = 0;
        __syncthreads();
        #pragma unroll
        for (int i = 0; i < VPT; i++) {
            float f = v[i];
            if (f >= lo && f < hi) {
                int idx = atomicAdd(&s_ncand, 1);
                if (idx < CAND_MAX) s_cand[idx] = f;
            }
        }
        __syncthreads();
        int m = s_ncand;              // == clo - chi  (<= CAND_MAX)
        int j = K_SEL - chi;          // 1-indexed descending rank among candidates
        if (t < m) {
            float vi = s_cand[t];
            int gt = 0, ge = 0;
            for (int c2 = 0; c2 < m; c2++) {
                float fc = s_cand[c2];
                gt += (fc >  vi);
                ge += (fc >= vi);
            }
            if (gt < j && j <= ge) s_thresh = vi;   // unique value; ties write same bits
        }
        __syncthreads();
        thresh = s_thresh;
    }

    // ---- mask in place, masked sum -> scale ----
    float s = 0.f;
    #pragma unroll
    for (int i = 0; i < VPT; i++) {
        float mv = (v[i] >= thresh) ? v[i] : 0.f;
        v[i] = mv;
        s += mv;
    }
    #pragma unroll
    for (int o = 16; o > 0; o >>= 1) s += __shfl_xor_sync(0xffffffffu, s, o);
    if (lane == 0) s_redf[wid] = s;
    __syncthreads();
    float tot = 0.f;
    #pragma unroll
    for (int i = 0; i < NWARP; i++) tot += s_redf[i];

    float scale = (float)D_COLS / tot;   // out = res / (sum/D) = res * D / sum

    // ---- scale + coalesced store ----
    #pragma unroll
    for (int i = 0; i < 4; i++) {
        float4 o;
        o.x = v[4*i+0] * scale;
        o.y = v[4*i+1] * scale;
        o.z = v[4*i+2] * scale;
        o.w = v[4*i+3] * scale;
        orow[t + i * NTHREADS] = o;
    }
}

extern "C" void kernel_launch(void* const* d_in, const int* in_sizes, int n_in,
                              void* d_out, int out_size)
{
    const float* x = (const float*)d_in[0];
    float* out     = (float*)d_out;
    int rows = in_sizes[0] / D_COLS;     // 16384
    sparsify1d_kernel<<<rows, NTHREADS>>>(x, out);
}

// round 4
// speedup vs baseline: 1.5322x; 1.2356x over previous
#include <cuda_runtime.h>

#define D_COLS   4096
#define K_SEL    2048
#define NTHREADS 128
#define VPT      32               // D_COLS / NTHREADS
#define NWARP    (NTHREADS / 32)  // 4
#define CAND_MAX 128

// Monotone float <-> ordered-uint key mapping (total order matching float <)
__device__ __forceinline__ unsigned fkey(float f) {
    unsigned u = __float_as_uint(f);
    return u ^ ((u & 0x80000000u) ? 0xFFFFFFFFu : 0x80000000u);
}
__device__ __forceinline__ float funkey(unsigned k) {
    unsigned u = k ^ ((k & 0x80000000u) ? 0x80000000u : 0xFFFFFFFFu);
    return __uint_as_float(u);
}
__device__ __forceinline__ bool my_finite(float f) { return fabsf(f) < 3.0e38f; }

// block count of (v >= T): REDUX per warp, lane0 -> smem, one LDS.128 broadcast
__device__ __forceinline__ int block_count(const float* v, float T,
                                           int4* s_slot, int lane, int wid)
{
    int c0 = 0, c1 = 0, c2 = 0, c3 = 0;
    #pragma unroll
    for (int i = 0; i < VPT; i += 4) {
        c0 += (v[i+0] >= T);
        c1 += (v[i+1] >= T);
        c2 += (v[i+2] >= T);
        c3 += (v[i+3] >= T);
    }
    int cc = (c0 + c1) + (c2 + c3);
    cc = __reduce_add_sync(0xffffffffu, cc);
    if (lane == 0) ((int*)s_slot)[wid] = cc;
    __syncthreads();
    int4 p = *s_slot;
    return (p.x + p.y) + (p.z + p.w);
}

__global__ __launch_bounds__(NTHREADS) void sparsify1d_kernel(
    const float* __restrict__ x, float* __restrict__ out)
{
    __shared__ __align__(16) int4  s_redi[2];
    __shared__ __align__(16) float s_redf[NWARP];
    __shared__ float s_thresh;
    __shared__ int   s_ncand;
    __shared__ float s_cand[CAND_MAX];

    const int t    = threadIdx.x;
    const int lane = t & 31;
    const int wid  = t >> 5;
    const long long row = blockIdx.x;

    const float4* __restrict__ xr   = (const float4*)(x + row * (long long)D_COLS);
    float4* __restrict__       orow = (float4*)(out + row * (long long)D_COLS);

    // ---- load row into registers (8 x float4, coalesced) ----
    float v[VPT];
    #pragma unroll
    for (int i = 0; i < 8; i++) {
        float4 f4 = xr[t + i * NTHREADS];
        v[4*i+0] = f4.x; v[4*i+1] = f4.y; v[4*i+2] = f4.z; v[4*i+3] = f4.w;
    }

    // ---- first probe at T0 = 0 (median of N(0,1) row) ----
    int c0 = block_count(v, 0.0f, &s_redi[0], lane, wid);

    // ---- bracket: count(>=lo)=clo >= K > chi=count(>=hi) ----
    float lo, hi; int clo, chi;
    if (c0 >= K_SEL) { lo = 0.0f; clo = c0;  hi = __int_as_float(0x7f800000); chi = 0; }
    else             { hi = 0.0f; chi = c0;  lo = __int_as_float(0xff800000); clo = D_COLS; }

    float thresh = 0.f;
    bool  have_thresh = false;
    int   par = 1;

    for (int iter = 0; iter < 48; iter++) {
        int m = clo - chi;
        if (m <= CAND_MAX) break;

        unsigned klo = fkey(lo), khi = fkey(hi);
        if (khi - klo <= 1u) { thresh = lo; have_thresh = true; break; }

        float T = lo;
        bool ok = false;
        if (iter < 10) {
            bool lof = my_finite(lo), hif = my_finite(hi);
            if (lof && hif) {
                T = lo + (hi - lo) * ((float)(clo - K_SEL) / (float)m);
            } else if (lof) {
                float dens = (float)D_COLS * 0.39894228f * __expf(-0.5f * lo * lo);
                T = lo + (float)(clo - K_SEL) / dens;
            } else {
                float dens = (float)D_COLS * 0.39894228f * __expf(-0.5f * hi * hi);
                T = hi - (float)(K_SEL - chi) / dens;
            }
            ok = (T > lo) && (T < hi);            // rejects NaN / no-progress
        }
        if (!ok) T = funkey(klo + ((khi - klo) >> 1u));   // guaranteed progress

        int cc = block_count(v, T, &s_redi[par], lane, wid);
        par ^= 1;

        if (cc >= K_SEL) { lo = T; clo = cc; }
        else             { hi = T; chi = cc; }
    }

    if (!have_thresh) {
        // ---- gather candidates in [lo, hi); pick exact (K - chi)-th largest ----
        if (t == 0) s_ncand = 0;
        __syncthreads();
        #pragma unroll
        for (int i = 0; i < VPT; i++) {
            float f = v[i];
            if (f >= lo && f < hi) {
                int idx = atomicAdd(&s_ncand, 1);
                if (idx < CAND_MAX) s_cand[idx] = f;
            }
        }
        __syncthreads();
        int m = s_ncand;              // == clo - chi  (<= CAND_MAX)
        int j = K_SEL - chi;          // 1-indexed descending rank among candidates
        if (t < m) {
            float vi = s_cand[t];
            int gt = 0, ge = 0;
            for (int c2 = 0; c2 < m; c2++) {
                float fc = s_cand[c2];
                gt += (fc >  vi);
                ge += (fc >= vi);
            }
            if (gt < j && j <= ge) s_thresh = vi;   // ties write identical bits
        }
        __syncthreads();
        thresh = s_thresh;
    }

    // ---- mask in place, masked sum -> scale ----
    float s0 = 0.f, s1 = 0.f, s2 = 0.f, s3 = 0.f;
    #pragma unroll
    for (int i = 0; i < VPT; i += 4) {
        float m0 = (v[i+0] >= thresh) ? v[i+0] : 0.f;
        float m1 = (v[i+1] >= thresh) ? v[i+1] : 0.f;
        float m2 = (v[i+2] >= thresh) ? v[i+2] : 0.f;
        float m3 = (v[i+3] >= thresh) ? v[i+3] : 0.f;
        v[i+0] = m0; v[i+1] = m1; v[i+2] = m2; v[i+3] = m3;
        s0 += m0; s1 += m1; s2 += m2; s3 += m3;
    }
    float s = (s0 + s1) + (s2 + s3);
    #pragma unroll
    for (int o = 16; o > 0; o >>= 1) s += __shfl_xor_sync(0xffffffffu, s, o);
    if (lane == 0) s_redf[wid] = s;
    __syncthreads();
    float4 pf = *(const float4*)s_redf;
    float tot = (pf.x + pf.y) + (pf.z + pf.w);

    float scale = (float)D_COLS / tot;   // out = res / (sum/D) = res * D / sum

    // ---- scale + coalesced store ----
    #pragma unroll
    for (int i = 0; i < 8; i++) {
        float4 o;
        o.x = v[4*i+0] * scale;
        o.y = v[4*i+1] * scale;
        o.z = v[4*i+2] * scale;
        o.w = v[4*i+3] * scale;
        orow[t + i * NTHREADS] = o;
    }
}

extern "C" void kernel_launch(void* const* d_in, const int* in_sizes, int n_in,
                              void* d_out, int out_size)
{
    const float* x = (const float*)d_in[0];
    float* out     = (float*)d_out;
    int rows = in_sizes[0] / D_COLS;     // 16384
    sparsify1d_kernel<<<rows, NTHREADS>>>(x, out);
}